// round 15
// baseline (speedup 1.0000x reference)
#include <cuda_runtime.h>
#include <cuda_bf16.h>
#include <cstdint>
#include <math.h>

#define B_ 32
#define NN 131072
#define NEG 0.2f
typedef unsigned long long ull;

__device__ __align__(16) float g_qs[B_ * 512 * 3];
__device__ __align__(16) float g_q1[B_ * 256 * 3];
__device__ __align__(16) float g_q2[B_ * 128 * 3];
__device__ __align__(16) __nv_bfloat16 g_xhi[(size_t)NN * 192];
__device__ __align__(16) __nv_bfloat16 g_xlo[(size_t)NN * 192];
__device__ __align__(16) float g_gate[NN];
__device__ __align__(16) float g_ya[(size_t)NN * 128];
__device__ __align__(16) float g_yb[(size_t)NN * 256];
__device__ __align__(16) __nv_bfloat16 g_f1h[B_ * 256 * 128];
__device__ __align__(16) __nv_bfloat16 g_f1l[B_ * 256 * 128];
__device__ __align__(16) __nv_bfloat16 g_wh[69632];
__device__ __align__(16) __nv_bfloat16 g_wl[69632];
__device__ float2 g_stats4[4 * 256];

__device__ __forceinline__ void split2(float v, __nv_bfloat16& h, __nv_bfloat16& l) {
    h = __float2bfloat16(v);
    l = __float2bfloat16(v - __bfloat162float(h));
}
__device__ __forceinline__ unsigned pack_bf2(__nv_bfloat16 a, __nv_bfloat16 b) {
    unsigned short ua = *(unsigned short*)&a, ub = *(unsigned short*)&b;
    return (unsigned)ua | ((unsigned)ub << 16);
}
__device__ __forceinline__ unsigned smem_u32(const void* p) {
    unsigned a;
    asm("{ .reg .u64 t; cvta.to.shared.u64 t, %1; cvt.u32.u64 %0, t; }" : "=r"(a) : "l"(p));
    return a;
}
__device__ __forceinline__ void ldsm4(unsigned* r, unsigned addr) {
    asm volatile("ldmatrix.sync.aligned.m8n8.x4.shared.b16 {%0,%1,%2,%3}, [%4];"
                 : "=r"(r[0]), "=r"(r[1]), "=r"(r[2]), "=r"(r[3]) : "r"(addr));
}
__device__ __forceinline__ void mma_bf16(float* c, const unsigned* a, const unsigned* b) {
    asm volatile("mma.sync.aligned.m16n8k16.row.col.f32.bf16.bf16.f32 "
                 "{%0,%1,%2,%3}, {%4,%5,%6,%7}, {%8,%9}, {%0,%1,%2,%3};"
                 : "+f"(c[0]), "+f"(c[1]), "+f"(c[2]), "+f"(c[3])
                 : "r"(a[0]), "r"(a[1]), "r"(a[2]), "r"(a[3]), "r"(b[0]), "r"(b[1]));
}
#define SW(x) ((x) ^ (((x) >> 3) & 0x70u))

// ---------------- shift_point (verified) ----------------
__global__ void shift_kernel(const float* __restrict__ xyz, float* __restrict__ q, int N) {
    int i = blockIdx.x * blockDim.x + threadIdx.x;
    if (i >= B_ * N) return;
    int b = i / N, n = i - b * N;
    if ((b & 15) < 15) {
        const float* s = xyz + ((size_t)(b + 1) * N + n) * 3;
        float* d = q + (size_t)i * 3;
        d[0] = s[0]; d[1] = s[1]; d[2] = s[2];
    } else {
        int b0 = b - 15;
        #pragma unroll
        for (int c = 0; c < 3; c++) {
            float s = 0.f;
            for (int t = 0; t < 15; t++)
                s = __fadd_rn(s, __fsub_rn(xyz[((size_t)(b0 + t + 1) * N + n) * 3 + c],
                                           xyz[((size_t)(b0 + t) * N + n) * 3 + c]));
            q[(size_t)i * 3 + c] = __fadd_rn(xyz[((size_t)b * N + n) * 3 + c],
                                             __fdiv_rn(s, 15.f));
        }
    }
}

// ---------------- FPS: redux.sync warp reduce (verified round 12) -------------
template <int PPT>
__global__ void fps_kernel(const float* __restrict__ q, float* __restrict__ qsel, int NP) {
    const int N = PPT * 128;
    __shared__ float sx[512], sy[512], sz[512];
    __shared__ ull wk[2][4];
    int b = blockIdx.x, tid = threadIdx.x, w = tid >> 5;
    const float* qb = q + (size_t)b * N * 3;
    float px[PPT], py[PPT], pz[PPT], mind[PPT];
    #pragma unroll
    for (int p = 0; p < PPT; p++) {
        int j = tid + 128 * p;
        px[p] = qb[j * 3 + 0]; py[p] = qb[j * 3 + 1]; pz[p] = qb[j * 3 + 2];
        sx[j] = px[p]; sy[j] = py[p]; sz[j] = pz[p];
        mind[p] = 1e10f;
    }
    __syncthreads();
    float lx = sx[0], ly = sy[0], lz = sz[0];
    if (tid == 0) {
        float* d = qsel + (size_t)b * NP * 3;
        d[0] = lx; d[1] = ly; d[2] = lz;
    }
    for (int t = 1; t < NP; t++) {
        unsigned bbits = 0u;
        int bidx = N;
        #pragma unroll
        for (int p = 0; p < PPT; p++) {
            float dx = __fsub_rn(px[p], lx), dy = __fsub_rn(py[p], ly), dz = __fsub_rn(pz[p], lz);
            float d = __fadd_rn(__fadd_rn(__fmul_rn(dx, dx), __fmul_rn(dy, dy)),
                                __fmul_rn(dz, dz));
            mind[p] = fminf(mind[p], d);
            unsigned kb = __float_as_uint(mind[p]);
            int gi = tid + 128 * p;
            if (kb > bbits || (kb == bbits && gi < bidx)) { bbits = kb; bidx = gi; }
        }
        unsigned wb = __reduce_max_sync(0xffffffffu, bbits);
        int cand = (bbits == wb) ? bidx : 0x7FFFFFFF;
        int wi = __reduce_min_sync(0xffffffffu, (unsigned)cand);
        int par = t & 1;
        if ((tid & 31) == 0)
            wk[par][w] = (((ull)wb) << 32) | (unsigned)(N - 1 - wi);
        __syncthreads();
        ull best = wk[par][0];
        #pragma unroll
        for (int i = 1; i < 4; i++) { ull o = wk[par][i]; if (o > best) best = o; }
        int bi = N - 1 - (int)(best & 0xffffffffu);
        lx = sx[bi]; ly = sy[bi]; lz = sz[bi];
        if (tid == 0) {
            float* d2 = qsel + ((size_t)b * NP + t) * 3;
            d2[0] = lx; d2[1] = ly; d2[2] = lz;
        }
    }
}

// ---- ball query + bf16 hi/lo X rows + gate (verified) ----
__global__ void group_kernel(const float* __restrict__ q, int M,
                             const float* __restrict__ sup, int N,
                             const __nv_bfloat16* __restrict__ fhi,
                             const __nv_bfloat16* __restrict__ flo,
                             float r2, float radius, int K, int P,
                             __nv_bfloat16* __restrict__ xhi,
                             __nv_bfloat16* __restrict__ xlo,
                             float* __restrict__ gate) {
    int gw = (blockIdx.x * blockDim.x + threadIdx.x) >> 5;
    int lane = threadIdx.x & 31;
    int wl = threadIdx.x >> 5;
    __shared__ int slist[8][32];
    if (gw >= B_ * M) return;
    int b = gw / M, m = gw - b * M;
    const float* qp = q + ((size_t)b * M + m) * 3;
    float qx = qp[0], qy = qp[1], qz = qp[2];
    const float* xb = sup + (size_t)b * N * 3;
    int count = 0;
    for (int base = 0; base < N; base += 32) {
        int j = base + lane;
        float dx = __fsub_rn(qx, xb[j * 3 + 0]);
        float dy = __fsub_rn(qy, xb[j * 3 + 1]);
        float dz = __fsub_rn(qz, xb[j * 3 + 2]);
        float d2 = __fadd_rn(__fadd_rn(__fmul_rn(dx, dx), __fmul_rn(dy, dy)),
                             __fmul_rn(dz, dz));
        bool in = d2 < r2;
        unsigned bal = __ballot_sync(0xffffffffu, in);
        int pos = count + __popc(bal & ((1u << lane) - 1u));
        if (in && pos < K) slist[wl][pos] = j;
        count += __popc(bal);
        if (count >= K) break;
    }
    if (count > K) count = K;
    __syncwarp();
    int pad = (count > 0) ? slist[wl][0] : 0;
    if (lane < K && lane >= count) slist[wl][lane] = pad;
    __syncwarp();
    int nb = (b * M + m) * K;
    if (lane < K) {
        int j = slist[wl][lane];
        float gx = xb[j * 3 + 0], gy = xb[j * 3 + 1], gz = xb[j * 3 + 2];
        float dpx = (gx - qx) / radius, dpy = (gy - qy) / radius, dpz = (gz - qz) / radius;
        float dist = sqrtf(dpx * dpx + dpy * dpy + dpz * dpz);
        gate[nb + lane] = 1.0f / (1.0f + expf(-dist));
        size_t r = (size_t)(nb + lane) * P;
        __nv_bfloat16* rh = xhi + r;
        __nv_bfloat16* rl = xlo + r;
        __nv_bfloat16 h0, l0, h1, l1;
        uint4 z = {0, 0, 0, 0};
        if (!fhi) {
            split2(dpx, h0, l0); split2(dpy, h1, l1);
            *(unsigned*)(rh + 0) = pack_bf2(h0, h1); *(unsigned*)(rl + 0) = pack_bf2(l0, l1);
            split2(dpz, h0, l0); split2(gx, h1, l1);
            *(unsigned*)(rh + 2) = pack_bf2(h0, h1); *(unsigned*)(rl + 2) = pack_bf2(l0, l1);
            split2(gy, h0, l0); split2(gz, h1, l1);
            *(unsigned*)(rh + 4) = pack_bf2(h0, h1); *(unsigned*)(rl + 4) = pack_bf2(l0, l1);
            *(unsigned*)(rh + 6) = 0u; *(unsigned*)(rl + 6) = 0u;
            uint4* zh = (uint4*)(rh + 8);
            uint4* zl = (uint4*)(rl + 8);
            #pragma unroll
            for (int i = 0; i < 7; i++) { zh[i] = z; zl[i] = z; }
        } else {
            const uint4* sh4 = (const uint4*)(fhi + ((size_t)b * 256 + j) * 128);
            const uint4* sl4 = (const uint4*)(flo + ((size_t)b * 256 + j) * 128);
            uint4* dh4 = (uint4*)rh;
            uint4* dl4 = (uint4*)rl;
            #pragma unroll
            for (int i = 0; i < 16; i++) { dh4[i] = sh4[i]; dl4[i] = sl4[i]; }
            split2(dpx, h0, l0); split2(dpy, h1, l1);
            *(unsigned*)(rh + 128) = pack_bf2(h0, h1); *(unsigned*)(rl + 128) = pack_bf2(l0, l1);
            __nv_bfloat16 zb = __float2bfloat16(0.f);
            split2(dpz, h0, l0);
            *(unsigned*)(rh + 130) = pack_bf2(h0, zb); *(unsigned*)(rl + 130) = pack_bf2(l0, zb);
            *(unsigned*)(rh + 132) = 0u; *(unsigned*)(rl + 132) = 0u;
            *(unsigned*)(rh + 134) = 0u; *(unsigned*)(rl + 134) = 0u;
            uint4* zh = (uint4*)(rh + 136);
            uint4* zl = (uint4*)(rl + 136);
            #pragma unroll
            for (int i = 0; i < 7; i++) { zh[i] = z; zl[i] = z; }
        }
    }
}

// ---------------- W split + 2a permutation ----------------
__global__ void wsplit_kernel(const float* __restrict__ w1a, const float* __restrict__ w1b,
                              const float* __restrict__ w2a, const float* __restrict__ w2b,
                              __nv_bfloat16* __restrict__ wh, __nv_bfloat16* __restrict__ wl) {
    int L = blockIdx.x;
    const float* src = L == 0 ? w1a : L == 1 ? w1b : L == 2 ? w2a : w2b;
    int O   = L == 0 ? 64 : L == 1 ? 128 : L == 2 ? 128 : 256;
    int Cs  = L == 0 ? 6  : L == 1 ? 64  : L == 2 ? 131 : 128;
    int Kst = L == 0 ? 64 : L == 1 ? 64  : L == 2 ? 192 : 128;
    int off = L == 0 ? 0  : L == 1 ? 4096 : L == 2 ? 12288 : 36864;
    for (int idx = threadIdx.x; idx < O * Kst; idx += blockDim.x) {
        int o = idx / Kst, c = idx - o * Kst;
        int scol;
        if (L == 2) scol = (c < 128) ? (3 + c) : (c < 131) ? (c - 128) : -1;
        else        scol = (c < Cs) ? c : -1;
        float v = (scol >= 0) ? src[o * Cs + scol] : 0.f;
        __nv_bfloat16 h, l;
        split2(v, h, l);
        wh[off + idx] = h;
        wl[off + idx] = l;
    }
}

// ---------------- HMMA GEMM (verified loop) + zero-k-step skipping ------------
// smem: Ahi[128][64] @0, Alo @16384, Bhi[64][64] @32768, Blo @40960, red @49152
__device__ __forceinline__ void mma_step(unsigned sb, float (&acc)[2][4][4],
                                         int lane, int wm, int wn, int k0) {
    const unsigned AH = 0, AL = 16384, BH = 32768, BL = 40960;
    unsigned ah[2][4], al[2][4];
    {
        int arow = lane & 15, akk = k0 + ((lane >> 4) << 3);
        #pragma unroll
        for (int mf = 0; mf < 2; mf++) {
            unsigned byte = (unsigned)((wm * 32 + mf * 16 + arow) * 128 + akk * 2);
            unsigned sw = SW(byte);
            ldsm4(ah[mf], sb + AH + sw);
            ldsm4(al[mf], sb + AL + sw);
        }
    }
    unsigned bh[4][2], bl[4][2];
    {
        int brow = ((lane >> 4) << 3) + (lane & 7);
        int bkk = k0 + (((lane >> 3) & 1) << 3);
        #pragma unroll
        for (int nf16 = 0; nf16 < 2; nf16++) {
            unsigned byte = (unsigned)((wn * 32 + nf16 * 16 + brow) * 128 + bkk * 2);
            unsigned sw = SW(byte);
            unsigned t[4];
            ldsm4(t, sb + BH + sw);
            bh[nf16 * 2][0] = t[0]; bh[nf16 * 2][1] = t[1];
            bh[nf16 * 2 + 1][0] = t[2]; bh[nf16 * 2 + 1][1] = t[3];
            ldsm4(t, sb + BL + sw);
            bl[nf16 * 2][0] = t[0]; bl[nf16 * 2][1] = t[1];
            bl[nf16 * 2 + 1][0] = t[2]; bl[nf16 * 2 + 1][1] = t[3];
        }
    }
    #pragma unroll
    for (int mf = 0; mf < 2; mf++)
        #pragma unroll
        for (int nf = 0; nf < 4; nf++) {
            mma_bf16(acc[mf][nf], ah[mf], bh[nf]);
            mma_bf16(acc[mf][nf], ah[mf], bl[nf]);
            mma_bf16(acc[mf][nf], al[mf], bh[nf]);
        }
}

__global__ void __launch_bounds__(256) hgemm(
    const __nv_bfloat16* __restrict__ Ahi, const __nv_bfloat16* __restrict__ Alo,
    const __nv_bfloat16* __restrict__ Bhi, const __nv_bfloat16* __restrict__ Blo,
    float* __restrict__ Y, int O, int Kst, int Cvalid, float2* __restrict__ st) {
    extern __shared__ char smem[];
    unsigned sb = smem_u32(smem);
    const unsigned AH = 0, AL = 16384, BH = 32768, BL = 40960;
    int tid = threadIdx.x, wid = tid >> 5, lane = tid & 31;
    int wm = wid & 3, wn = wid >> 2;
    size_t mbase = (size_t)blockIdx.y * 128;    // m-tile on y (slow)
    int nbase = blockIdx.x * 64;                 // n-tile on x (fast) -> A reuse in L2

    float acc[2][4][4];
    #pragma unroll
    for (int i = 0; i < 2; i++)
        #pragma unroll
        for (int j = 0; j < 4; j++)
            #pragma unroll
            for (int r = 0; r < 4; r++) acc[i][j][r] = 0.f;

    for (int kb = 0; kb < Kst; kb += 64) {
        int rem = Cvalid - kb;
        int steps = (rem >= 64) ? 4 : ((rem + 15) >> 4);   // 1..4 for our shapes
        int kcmax = steps * 2;
        __syncthreads();
        for (int i = tid; i < 1024; i += 256) {
            int r = i >> 3, kc = i & 7;
            if (kc < kcmax) {
                unsigned sw = SW((unsigned)(r * 128 + kc * 16));
                const __nv_bfloat16* sa = Ahi + (mbase + r) * Kst + kb + kc * 8;
                const __nv_bfloat16* sl = Alo + (mbase + r) * Kst + kb + kc * 8;
                asm volatile("cp.async.ca.shared.global [%0], [%1], 16;" :: "r"(sb + AH + sw), "l"(sa));
                asm volatile("cp.async.ca.shared.global [%0], [%1], 16;" :: "r"(sb + AL + sw), "l"(sl));
            }
        }
        for (int i = tid; i < 512; i += 256) {
            int r = i >> 3, kc = i & 7;
            if (kc < kcmax) {
                unsigned sw = SW((unsigned)(r * 128 + kc * 16));
                const __nv_bfloat16* sa = Bhi + (size_t)(nbase + r) * Kst + kb + kc * 8;
                const __nv_bfloat16* sl = Blo + (size_t)(nbase + r) * Kst + kb + kc * 8;
                asm volatile("cp.async.ca.shared.global [%0], [%1], 16;" :: "r"(sb + BH + sw), "l"(sa));
                asm volatile("cp.async.ca.shared.global [%0], [%1], 16;" :: "r"(sb + BL + sw), "l"(sl));
            }
        }
        asm volatile("cp.async.commit_group;");
        asm volatile("cp.async.wait_group 0;");
        __syncthreads();

        if (steps == 4) {
            mma_step(sb, acc, lane, wm, wn, 0);
            mma_step(sb, acc, lane, wm, wn, 16);
            mma_step(sb, acc, lane, wm, wn, 32);
            mma_step(sb, acc, lane, wm, wn, 48);
        } else {
            mma_step(sb, acc, lane, wm, wn, 0);
            if (steps > 1) {
                mma_step(sb, acc, lane, wm, wn, 16);
                if (steps > 2) mma_step(sb, acc, lane, wm, wn, 32);
            }
        }
    }

    // epilogue 1: point-major Y stores
    int g = lane >> 2, tg = lane & 3;
    #pragma unroll
    for (int mf = 0; mf < 2; mf++) {
        size_t row0 = mbase + wm * 32 + mf * 16;
        #pragma unroll
        for (int nf = 0; nf < 4; nf++) {
            int col = nbase + wn * 32 + nf * 8 + tg * 2;
            float2 v0 = {acc[mf][nf][0], acc[mf][nf][1]};
            float2 v1 = {acc[mf][nf][2], acc[mf][nf][3]};
            *(float2*)(Y + (row0 + g) * O + col) = v0;
            *(float2*)(Y + (row0 + 8 + g) * O + col) = v1;
        }
    }

    // epilogue 2: per-channel sum/sumsq, smem-staged, few global atomics
    float* red = (float*)(smem + 49152);
    __syncthreads();
    if (tid < 128) red[tid] = 0.f;
    __syncthreads();
    #pragma unroll
    for (int nf = 0; nf < 4; nf++) {
        #pragma unroll
        for (int c = 0; c < 2; c++) {
            float s = (acc[0][nf][c] + acc[0][nf][c + 2]) +
                      (acc[1][nf][c] + acc[1][nf][c + 2]);
            float q = (acc[0][nf][c] * acc[0][nf][c] + acc[0][nf][c + 2] * acc[0][nf][c + 2]) +
                      (acc[1][nf][c] * acc[1][nf][c] + acc[1][nf][c + 2] * acc[1][nf][c + 2]);
            #pragma unroll
            for (int off = 4; off < 32; off <<= 1) {
                s += __shfl_xor_sync(0xffffffffu, s, off);
                q += __shfl_xor_sync(0xffffffffu, q, off);
            }
            if (g == 0) {
                int lc = wn * 32 + nf * 8 + lane * 2 + c;
                atomicAdd(&red[2 * lc], s);
                atomicAdd(&red[2 * lc + 1], q);
            }
        }
    }
    __syncthreads();
    if (tid < 64) {
        atomicAdd(&st[nbase + tid].x, red[2 * tid]);
        atomicAdd(&st[nbase + tid].y, red[2 * tid + 1]);
    }
}

// ---------------- BN + lrelu + bf16 hi/lo split (a-layers) ----------------
__global__ void bn_split(const float* __restrict__ Y, const float2* __restrict__ st,
                         const float* __restrict__ gg, const float* __restrict__ bb,
                         int O, __nv_bfloat16* __restrict__ xh, __nv_bfloat16* __restrict__ xl) {
    size_t i4 = ((size_t)blockIdx.x * blockDim.x + threadIdx.x) * 4;
    int c0 = (int)(i4 & (size_t)(O - 1));
    float4 v = *(const float4*)(Y + i4);
    float o[4] = {v.x, v.y, v.z, v.w};
    __nv_bfloat16 h[4], l[4];
    #pragma unroll
    for (int j = 0; j < 4; j++) {
        int c = c0 + j;
        float2 s = st[c];
        float mu = s.x * (1.f / NN);
        float var = s.y * (1.f / NN) - mu * mu;
        float sc = rsqrtf(var + 1e-5f) * gg[c];
        float sh = bb[c] - mu * sc;
        float t = fmaf(o[j], sc, sh);
        t = t > 0.f ? t : NEG * t;
        split2(t, h[j], l[j]);
    }
    *(unsigned*)(xh + i4 + 0) = pack_bf2(h[0], h[1]);
    *(unsigned*)(xh + i4 + 2) = pack_bf2(h[2], h[3]);
    *(unsigned*)(xl + i4 + 0) = pack_bf2(l[0], l[1]);
    *(unsigned*)(xl + i4 + 2) = pack_bf2(l[2], l[3]);
}

// ---------------- BN + lrelu + gate + max over K (b-layers) ----------------
__global__ void bnmax_kernel(const float* __restrict__ Y, const float2* __restrict__ st,
                             const float* __restrict__ gg, const float* __restrict__ bb,
                             const float* __restrict__ gate, int M, int K, int O,
                             float* __restrict__ outf,
                             __nv_bfloat16* __restrict__ fh, __nv_bfloat16* __restrict__ fl) {
    int gw = (blockIdx.x * blockDim.x + threadIdx.x) >> 5;
    int lane = threadIdx.x & 31;
    if (gw >= B_ * M) return;
    int b = gw / M, m = gw - b * M;
    int base = gw * K;
    int J = O >> 5;
    float mx[8], sc[8], sh[8];
    for (int j = 0; j < J; j++) {
        int c = lane + 32 * j;
        float2 s = st[c];
        float mu = s.x * (1.f / NN);
        float var = s.y * (1.f / NN) - mu * mu;
        sc[j] = rsqrtf(var + 1e-5f) * gg[c];
        sh[j] = bb[c] - mu * sc[j];
        mx[j] = -3.4e38f;
    }
    for (int k = 0; k < K; k++) {
        float gt = gate[base + k];
        const float* row = Y + (size_t)(base + k) * O;
        for (int j = 0; j < J; j++) {
            float t = fmaf(row[lane + 32 * j], sc[j], sh[j]);
            t = t > 0.f ? t : NEG * t;
            mx[j] = fmaxf(mx[j], gt * t);
        }
    }
    if (fh) {
        size_t r = ((size_t)b * M + m) * O;
        for (int j = 0; j < J; j++) {
            __nv_bfloat16 h, l;
            split2(mx[j], h, l);
            fh[r + lane + 32 * j] = h;
            fl[r + lane + 32 * j] = l;
        }
    } else {
        for (int j = 0; j < J; j++)
            outf[((size_t)b * O + lane + 32 * j) * M + m] = mx[j];
    }
}

extern "C" void kernel_launch(void* const* d_in, const int* in_sizes, int n_in,
                              void* d_out, int out_size) {
    const float* xyz = (const float*)d_in[0];
    const float* w1a = (const float*)d_in[1];
    const float* g1a = (const float*)d_in[2];
    const float* b1a = (const float*)d_in[3];
    const float* w1b = (const float*)d_in[4];
    const float* g1b = (const float*)d_in[5];
    const float* b1b = (const float*)d_in[6];
    const float* w2a = (const float*)d_in[7];
    const float* g2a = (const float*)d_in[8];
    const float* b2a = (const float*)d_in[9];
    const float* w2b = (const float*)d_in[10];
    const float* g2b = (const float*)d_in[11];
    const float* b2b = (const float*)d_in[12];

    float *qs, *q1, *q2, *gate, *ya, *yb;
    __nv_bfloat16 *xh, *xl, *f1h, *f1l, *wh, *wl;
    float2* st;
    cudaGetSymbolAddress((void**)&qs, g_qs);
    cudaGetSymbolAddress((void**)&q1, g_q1);
    cudaGetSymbolAddress((void**)&q2, g_q2);
    cudaGetSymbolAddress((void**)&xh, g_xhi);
    cudaGetSymbolAddress((void**)&xl, g_xlo);
    cudaGetSymbolAddress((void**)&gate, g_gate);
    cudaGetSymbolAddress((void**)&ya, g_ya);
    cudaGetSymbolAddress((void**)&yb, g_yb);
    cudaGetSymbolAddress((void**)&f1h, g_f1h);
    cudaGetSymbolAddress((void**)&f1l, g_f1l);
    cudaGetSymbolAddress((void**)&wh, g_wh);
    cudaGetSymbolAddress((void**)&wl, g_wl);
    cudaGetSymbolAddress((void**)&st, g_stats4);
    float2 *st1a = st, *st1b = st + 256, *st2a = st + 512, *st2b = st + 768;

    const int HSM = 49152 + 512;
    cudaFuncSetAttribute(hgemm, cudaFuncAttributeMaxDynamicSharedMemorySize, HSM);

    const float r2a = (float)(0.15 * 0.15);
    const float r2b = (float)(0.3 * 0.3);

    cudaMemsetAsync(st, 0, 4 * 256 * sizeof(float2), 0);
    wsplit_kernel<<<4, 256>>>(w1a, w1b, w2a, w2b, wh, wl);

    // ---------- stage 1 ----------
    shift_kernel<<<(B_ * 512 + 255) / 256, 256>>>(xyz, qs, 512);
    fps_kernel<4><<<B_, 128>>>(qs, q1, 256);
    group_kernel<<<1024, 256>>>(q1, 256, xyz, 512, (const __nv_bfloat16*)0,
                                (const __nv_bfloat16*)0, r2a, 0.15f, 16, 64, xh, xl, gate);
    hgemm<<<dim3(1, NN / 128), 256, HSM>>>(xh, xl, wh, wl, ya, 64, 64, 6, st1a);
    bn_split<<<(NN / 1024) * 64, 256>>>(ya, st1a, g1a, b1a, 64, xh, xl);
    hgemm<<<dim3(2, NN / 128), 256, HSM>>>(xh, xl, wh + 4096, wl + 4096, yb, 128, 64, 64, st1b);
    bnmax_kernel<<<1024, 256>>>(yb, st1b, g1b, b1b, gate, 256, 16, 128,
                                (float*)0, f1h, f1l);

    // ---------- stage 2 ----------
    shift_kernel<<<(B_ * 256 + 255) / 256, 256>>>(q1, qs, 256);
    fps_kernel<2><<<B_, 128>>>(qs, q2, 128);
    group_kernel<<<512, 256>>>(q2, 128, q1, 256, f1h, f1l, r2b, 0.3f, 32, 192,
                               xh, xl, gate);
    hgemm<<<dim3(2, NN / 128), 256, HSM>>>(xh, xl, wh + 12288, wl + 12288, ya, 128, 192, 131, st2a);
    bn_split<<<(NN / 1024) * 128, 256>>>(ya, st2a, g2a, b2a, 128, xh, xl);
    hgemm<<<dim3(4, NN / 128), 256, HSM>>>(xh, xl, wh + 36864, wl + 36864, yb, 256, 128, 128, st2b);
    bnmax_kernel<<<512, 256>>>(yb, st2b, g2b, b2b, gate, 128, 32, 256,
                               (float*)d_out, (__nv_bfloat16*)0, (__nv_bfloat16*)0);
}

// round 16
// speedup vs baseline: 1.0273x; 1.0273x over previous
#include <cuda_runtime.h>
#include <cuda_bf16.h>
#include <cstdint>
#include <math.h>

#define B_ 32
#define NN 131072
#define NEG 0.2f
typedef unsigned long long ull;

__device__ __align__(16) float g_qs[B_ * 512 * 3];
__device__ __align__(16) float g_q1[B_ * 256 * 3];
__device__ __align__(16) float g_q2[B_ * 128 * 3];
__device__ __align__(16) __nv_bfloat16 g_xhi[(size_t)NN * 192];
__device__ __align__(16) __nv_bfloat16 g_xlo[(size_t)NN * 192];
__device__ __align__(16) float g_gate[NN];
__device__ __align__(16) float g_ya[(size_t)NN * 128];
__device__ __align__(16) float g_yb[(size_t)NN * 256];
__device__ __align__(16) __nv_bfloat16 g_f1h[B_ * 256 * 128];
__device__ __align__(16) __nv_bfloat16 g_f1l[B_ * 256 * 128];
__device__ __align__(16) __nv_bfloat16 g_wh[69632];
__device__ __align__(16) __nv_bfloat16 g_wl[69632];
__device__ float2 g_stats4[4 * 256];

__device__ __forceinline__ void split2(float v, __nv_bfloat16& h, __nv_bfloat16& l) {
    h = __float2bfloat16(v);
    l = __float2bfloat16(v - __bfloat162float(h));
}
__device__ __forceinline__ unsigned pack_bf2(__nv_bfloat16 a, __nv_bfloat16 b) {
    unsigned short ua = *(unsigned short*)&a, ub = *(unsigned short*)&b;
    return (unsigned)ua | ((unsigned)ub << 16);
}
__device__ __forceinline__ unsigned smem_u32(const void* p) {
    unsigned a;
    asm("{ .reg .u64 t; cvta.to.shared.u64 t, %1; cvt.u32.u64 %0, t; }" : "=r"(a) : "l"(p));
    return a;
}
__device__ __forceinline__ void ldsm4(unsigned* r, unsigned addr) {
    asm volatile("ldmatrix.sync.aligned.m8n8.x4.shared.b16 {%0,%1,%2,%3}, [%4];"
                 : "=r"(r[0]), "=r"(r[1]), "=r"(r[2]), "=r"(r[3]) : "r"(addr));
}
__device__ __forceinline__ void mma_bf16(float* c, const unsigned* a, const unsigned* b) {
    asm volatile("mma.sync.aligned.m16n8k16.row.col.f32.bf16.bf16.f32 "
                 "{%0,%1,%2,%3}, {%4,%5,%6,%7}, {%8,%9}, {%0,%1,%2,%3};"
                 : "+f"(c[0]), "+f"(c[1]), "+f"(c[2]), "+f"(c[3])
                 : "r"(a[0]), "r"(a[1]), "r"(a[2]), "r"(a[3]), "r"(b[0]), "r"(b[1]));
}
#define SW(x) ((x) ^ (((x) >> 3) & 0x70u))

// ---------------- shift_point (verified) ----------------
__global__ void shift_kernel(const float* __restrict__ xyz, float* __restrict__ q, int N) {
    int i = blockIdx.x * blockDim.x + threadIdx.x;
    if (i >= B_ * N) return;
    int b = i / N, n = i - b * N;
    if ((b & 15) < 15) {
        const float* s = xyz + ((size_t)(b + 1) * N + n) * 3;
        float* d = q + (size_t)i * 3;
        d[0] = s[0]; d[1] = s[1]; d[2] = s[2];
    } else {
        int b0 = b - 15;
        #pragma unroll
        for (int c = 0; c < 3; c++) {
            float s = 0.f;
            for (int t = 0; t < 15; t++)
                s = __fadd_rn(s, __fsub_rn(xyz[((size_t)(b0 + t + 1) * N + n) * 3 + c],
                                           xyz[((size_t)(b0 + t) * N + n) * 3 + c]));
            q[(size_t)i * 3 + c] = __fadd_rn(xyz[((size_t)b * N + n) * 3 + c],
                                             __fdiv_rn(s, 15.f));
        }
    }
}

// ---------------- FPS: redux.sync warp reduce (verified round 12) -------------
template <int PPT>
__global__ void fps_kernel(const float* __restrict__ q, float* __restrict__ qsel, int NP) {
    const int N = PPT * 128;
    __shared__ float sx[512], sy[512], sz[512];
    __shared__ ull wk[2][4];
    int b = blockIdx.x, tid = threadIdx.x, w = tid >> 5;
    const float* qb = q + (size_t)b * N * 3;
    float px[PPT], py[PPT], pz[PPT], mind[PPT];
    #pragma unroll
    for (int p = 0; p < PPT; p++) {
        int j = tid + 128 * p;
        px[p] = qb[j * 3 + 0]; py[p] = qb[j * 3 + 1]; pz[p] = qb[j * 3 + 2];
        sx[j] = px[p]; sy[j] = py[p]; sz[j] = pz[p];
        mind[p] = 1e10f;
    }
    __syncthreads();
    float lx = sx[0], ly = sy[0], lz = sz[0];
    if (tid == 0) {
        float* d = qsel + (size_t)b * NP * 3;
        d[0] = lx; d[1] = ly; d[2] = lz;
    }
    for (int t = 1; t < NP; t++) {
        unsigned bbits = 0u;
        int bidx = N;
        #pragma unroll
        for (int p = 0; p < PPT; p++) {
            float dx = __fsub_rn(px[p], lx), dy = __fsub_rn(py[p], ly), dz = __fsub_rn(pz[p], lz);
            float d = __fadd_rn(__fadd_rn(__fmul_rn(dx, dx), __fmul_rn(dy, dy)),
                                __fmul_rn(dz, dz));
            mind[p] = fminf(mind[p], d);
            unsigned kb = __float_as_uint(mind[p]);
            int gi = tid + 128 * p;
            if (kb > bbits || (kb == bbits && gi < bidx)) { bbits = kb; bidx = gi; }
        }
        unsigned wb = __reduce_max_sync(0xffffffffu, bbits);
        int cand = (bbits == wb) ? bidx : 0x7FFFFFFF;
        int wi = __reduce_min_sync(0xffffffffu, (unsigned)cand);
        int par = t & 1;
        if ((tid & 31) == 0)
            wk[par][w] = (((ull)wb) << 32) | (unsigned)(N - 1 - wi);
        __syncthreads();
        ull best = wk[par][0];
        #pragma unroll
        for (int i = 1; i < 4; i++) { ull o = wk[par][i]; if (o > best) best = o; }
        int bi = N - 1 - (int)(best & 0xffffffffu);
        lx = sx[bi]; ly = sy[bi]; lz = sz[bi];
        if (tid == 0) {
            float* d2 = qsel + ((size_t)b * NP + t) * 3;
            d2[0] = lx; d2[1] = ly; d2[2] = lz;
        }
    }
}

// ---- ball query + bf16 hi/lo X rows + gate (verified) ----
__global__ void group_kernel(const float* __restrict__ q, int M,
                             const float* __restrict__ sup, int N,
                             const __nv_bfloat16* __restrict__ fhi,
                             const __nv_bfloat16* __restrict__ flo,
                             float r2, float radius, int K, int P,
                             __nv_bfloat16* __restrict__ xhi,
                             __nv_bfloat16* __restrict__ xlo,
                             float* __restrict__ gate) {
    int gw = (blockIdx.x * blockDim.x + threadIdx.x) >> 5;
    int lane = threadIdx.x & 31;
    int wl = threadIdx.x >> 5;
    __shared__ int slist[8][32];
    if (gw >= B_ * M) return;
    int b = gw / M, m = gw - b * M;
    const float* qp = q + ((size_t)b * M + m) * 3;
    float qx = qp[0], qy = qp[1], qz = qp[2];
    const float* xb = sup + (size_t)b * N * 3;
    int count = 0;
    for (int base = 0; base < N; base += 32) {
        int j = base + lane;
        float dx = __fsub_rn(qx, xb[j * 3 + 0]);
        float dy = __fsub_rn(qy, xb[j * 3 + 1]);
        float dz = __fsub_rn(qz, xb[j * 3 + 2]);
        float d2 = __fadd_rn(__fadd_rn(__fmul_rn(dx, dx), __fmul_rn(dy, dy)),
                             __fmul_rn(dz, dz));
        bool in = d2 < r2;
        unsigned bal = __ballot_sync(0xffffffffu, in);
        int pos = count + __popc(bal & ((1u << lane) - 1u));
        if (in && pos < K) slist[wl][pos] = j;
        count += __popc(bal);
        if (count >= K) break;
    }
    if (count > K) count = K;
    __syncwarp();
    int pad = (count > 0) ? slist[wl][0] : 0;
    if (lane < K && lane >= count) slist[wl][lane] = pad;
    __syncwarp();
    int nb = (b * M + m) * K;
    if (lane < K) {
        int j = slist[wl][lane];
        float gx = xb[j * 3 + 0], gy = xb[j * 3 + 1], gz = xb[j * 3 + 2];
        float dpx = (gx - qx) / radius, dpy = (gy - qy) / radius, dpz = (gz - qz) / radius;
        float dist = sqrtf(dpx * dpx + dpy * dpy + dpz * dpz);
        gate[nb + lane] = 1.0f / (1.0f + expf(-dist));
        size_t r = (size_t)(nb + lane) * P;
        __nv_bfloat16* rh = xhi + r;
        __nv_bfloat16* rl = xlo + r;
        __nv_bfloat16 h0, l0, h1, l1;
        uint4 z = {0, 0, 0, 0};
        if (!fhi) {
            split2(dpx, h0, l0); split2(dpy, h1, l1);
            *(unsigned*)(rh + 0) = pack_bf2(h0, h1); *(unsigned*)(rl + 0) = pack_bf2(l0, l1);
            split2(dpz, h0, l0); split2(gx, h1, l1);
            *(unsigned*)(rh + 2) = pack_bf2(h0, h1); *(unsigned*)(rl + 2) = pack_bf2(l0, l1);
            split2(gy, h0, l0); split2(gz, h1, l1);
            *(unsigned*)(rh + 4) = pack_bf2(h0, h1); *(unsigned*)(rl + 4) = pack_bf2(l0, l1);
            *(unsigned*)(rh + 6) = 0u; *(unsigned*)(rl + 6) = 0u;
            uint4* zh = (uint4*)(rh + 8);
            uint4* zl = (uint4*)(rl + 8);
            #pragma unroll
            for (int i = 0; i < 7; i++) { zh[i] = z; zl[i] = z; }
        } else {
            const uint4* sh4 = (const uint4*)(fhi + ((size_t)b * 256 + j) * 128);
            const uint4* sl4 = (const uint4*)(flo + ((size_t)b * 256 + j) * 128);
            uint4* dh4 = (uint4*)rh;
            uint4* dl4 = (uint4*)rl;
            #pragma unroll
            for (int i = 0; i < 16; i++) { dh4[i] = sh4[i]; dl4[i] = sl4[i]; }
            split2(dpx, h0, l0); split2(dpy, h1, l1);
            *(unsigned*)(rh + 128) = pack_bf2(h0, h1); *(unsigned*)(rl + 128) = pack_bf2(l0, l1);
            __nv_bfloat16 zb = __float2bfloat16(0.f);
            split2(dpz, h0, l0);
            *(unsigned*)(rh + 130) = pack_bf2(h0, zb); *(unsigned*)(rl + 130) = pack_bf2(l0, zb);
            *(unsigned*)(rh + 132) = 0u; *(unsigned*)(rl + 132) = 0u;
            *(unsigned*)(rh + 134) = 0u; *(unsigned*)(rl + 134) = 0u;
            uint4* zh = (uint4*)(rh + 136);
            uint4* zl = (uint4*)(rl + 136);
            #pragma unroll
            for (int i = 0; i < 7; i++) { zh[i] = z; zl[i] = z; }
        }
    }
}

// ---------------- W split + 2a permutation ----------------
__global__ void wsplit_kernel(const float* __restrict__ w1a, const float* __restrict__ w1b,
                              const float* __restrict__ w2a, const float* __restrict__ w2b,
                              __nv_bfloat16* __restrict__ wh, __nv_bfloat16* __restrict__ wl) {
    int L = blockIdx.x;
    const float* src = L == 0 ? w1a : L == 1 ? w1b : L == 2 ? w2a : w2b;
    int O   = L == 0 ? 64 : L == 1 ? 128 : L == 2 ? 128 : 256;
    int Cs  = L == 0 ? 6  : L == 1 ? 64  : L == 2 ? 131 : 128;
    int Kst = L == 0 ? 64 : L == 1 ? 64  : L == 2 ? 192 : 128;
    int off = L == 0 ? 0  : L == 1 ? 4096 : L == 2 ? 12288 : 36864;
    for (int idx = threadIdx.x; idx < O * Kst; idx += blockDim.x) {
        int o = idx / Kst, c = idx - o * Kst;
        int scol;
        if (L == 2) scol = (c < 128) ? (3 + c) : (c < 131) ? (c - 128) : -1;
        else        scol = (c < Cs) ? c : -1;
        float v = (scol >= 0) ? src[o * Cs + scol] : 0.f;
        __nv_bfloat16 h, l;
        split2(v, h, l);
        wh[off + idx] = h;
        wl[off + idx] = l;
    }
}

// ---------------- HMMA GEMM (round-13 exact) + fused BN-stat epilogue ---------
// smem: Ahi[128][64] @0, Alo @16384, Bhi[64][64] @32768, Blo @40960, red @49152
__global__ void __launch_bounds__(256) hgemm(
    const __nv_bfloat16* __restrict__ Ahi, const __nv_bfloat16* __restrict__ Alo,
    const __nv_bfloat16* __restrict__ Bhi, const __nv_bfloat16* __restrict__ Blo,
    float* __restrict__ Y, int O, int Kst, float2* __restrict__ st) {
    extern __shared__ char smem[];
    unsigned sb = smem_u32(smem);
    const unsigned AH = 0, AL = 16384, BH = 32768, BL = 40960;
    int tid = threadIdx.x, wid = tid >> 5, lane = tid & 31;
    int wm = wid & 3, wn = wid >> 2;
    size_t mbase = (size_t)blockIdx.y * 128;    // m-tile on y (slow)
    int nbase = blockIdx.x * 64;                 // n-tile on x (fast) -> A reuse in L2

    float acc[2][4][4];
    #pragma unroll
    for (int i = 0; i < 2; i++)
        #pragma unroll
        for (int j = 0; j < 4; j++)
            #pragma unroll
            for (int r = 0; r < 4; r++) acc[i][j][r] = 0.f;

    for (int kb = 0; kb < Kst; kb += 64) {
        __syncthreads();
        for (int i = tid; i < 1024; i += 256) {
            int r = i >> 3, kc = i & 7;
            unsigned sw = SW((unsigned)(r * 128 + kc * 16));
            const __nv_bfloat16* sa = Ahi + (mbase + r) * Kst + kb + kc * 8;
            const __nv_bfloat16* sl = Alo + (mbase + r) * Kst + kb + kc * 8;
            asm volatile("cp.async.ca.shared.global [%0], [%1], 16;" :: "r"(sb + AH + sw), "l"(sa));
            asm volatile("cp.async.ca.shared.global [%0], [%1], 16;" :: "r"(sb + AL + sw), "l"(sl));
        }
        for (int i = tid; i < 512; i += 256) {
            int r = i >> 3, kc = i & 7;
            unsigned sw = SW((unsigned)(r * 128 + kc * 16));
            const __nv_bfloat16* sa = Bhi + (size_t)(nbase + r) * Kst + kb + kc * 8;
            const __nv_bfloat16* sl = Blo + (size_t)(nbase + r) * Kst + kb + kc * 8;
            asm volatile("cp.async.ca.shared.global [%0], [%1], 16;" :: "r"(sb + BH + sw), "l"(sa));
            asm volatile("cp.async.ca.shared.global [%0], [%1], 16;" :: "r"(sb + BL + sw), "l"(sl));
        }
        asm volatile("cp.async.commit_group;");
        asm volatile("cp.async.wait_group 0;");
        __syncthreads();

        #pragma unroll
        for (int s = 0; s < 4; s++) {
            int k0 = s * 16;
            unsigned ah[2][4], al[2][4];
            {
                int arow = lane & 15, akk = k0 + ((lane >> 4) << 3);
                #pragma unroll
                for (int mf = 0; mf < 2; mf++) {
                    unsigned byte = (unsigned)((wm * 32 + mf * 16 + arow) * 128 + akk * 2);
                    unsigned sw = SW(byte);
                    ldsm4(ah[mf], sb + AH + sw);
                    ldsm4(al[mf], sb + AL + sw);
                }
            }
            unsigned bh[4][2], bl[4][2];
            {
                int brow = ((lane >> 4) << 3) + (lane & 7);
                int bkk = k0 + (((lane >> 3) & 1) << 3);
                #pragma unroll
                for (int nf16 = 0; nf16 < 2; nf16++) {
                    unsigned byte = (unsigned)((wn * 32 + nf16 * 16 + brow) * 128 + bkk * 2);
                    unsigned sw = SW(byte);
                    unsigned t[4];
                    ldsm4(t, sb + BH + sw);
                    bh[nf16 * 2][0] = t[0]; bh[nf16 * 2][1] = t[1];
                    bh[nf16 * 2 + 1][0] = t[2]; bh[nf16 * 2 + 1][1] = t[3];
                    ldsm4(t, sb + BL + sw);
                    bl[nf16 * 2][0] = t[0]; bl[nf16 * 2][1] = t[1];
                    bl[nf16 * 2 + 1][0] = t[2]; bl[nf16 * 2 + 1][1] = t[3];
                }
            }
            #pragma unroll
            for (int mf = 0; mf < 2; mf++)
                #pragma unroll
                for (int nf = 0; nf < 4; nf++) {
                    mma_bf16(acc[mf][nf], ah[mf], bh[nf]);
                    mma_bf16(acc[mf][nf], ah[mf], bl[nf]);
                    mma_bf16(acc[mf][nf], al[mf], bh[nf]);
                }
        }
    }

    // epilogue 1: point-major Y stores
    int g = lane >> 2, tg = lane & 3;
    #pragma unroll
    for (int mf = 0; mf < 2; mf++) {
        size_t row0 = mbase + wm * 32 + mf * 16;
        #pragma unroll
        for (int nf = 0; nf < 4; nf++) {
            int col = nbase + wn * 32 + nf * 8 + tg * 2;
            float2 v0 = {acc[mf][nf][0], acc[mf][nf][1]};
            float2 v1 = {acc[mf][nf][2], acc[mf][nf][3]};
            *(float2*)(Y + (row0 + g) * O + col) = v0;
            *(float2*)(Y + (row0 + 8 + g) * O + col) = v1;
        }
    }

    // epilogue 2: per-channel sum/sumsq, smem-staged, few global atomics
    float* red = (float*)(smem + 49152);
    __syncthreads();
    if (tid < 128) red[tid] = 0.f;
    __syncthreads();
    #pragma unroll
    for (int nf = 0; nf < 4; nf++) {
        #pragma unroll
        for (int c = 0; c < 2; c++) {
            float s = (acc[0][nf][c] + acc[0][nf][c + 2]) +
                      (acc[1][nf][c] + acc[1][nf][c + 2]);
            float q = (acc[0][nf][c] * acc[0][nf][c] + acc[0][nf][c + 2] * acc[0][nf][c + 2]) +
                      (acc[1][nf][c] * acc[1][nf][c] + acc[1][nf][c + 2] * acc[1][nf][c + 2]);
            #pragma unroll
            for (int off = 4; off < 32; off <<= 1) {
                s += __shfl_xor_sync(0xffffffffu, s, off);
                q += __shfl_xor_sync(0xffffffffu, q, off);
            }
            if (g == 0) {
                int lc = wn * 32 + nf * 8 + lane * 2 + c;
                atomicAdd(&red[2 * lc], s);
                atomicAdd(&red[2 * lc + 1], q);
            }
        }
    }
    __syncthreads();
    if (tid < 64) {
        atomicAdd(&st[nbase + tid].x, red[2 * tid]);
        atomicAdd(&st[nbase + tid].y, red[2 * tid + 1]);
    }
}

// ---------------- hgemm1a: specialized for layer 1a (O=64, Kst=64, C=6) -------
// Single k-tile, single k16-step, loads only first 16 of 64 k-channels.
__global__ void __launch_bounds__(256) hgemm1a(
    const __nv_bfloat16* __restrict__ Ahi, const __nv_bfloat16* __restrict__ Alo,
    const __nv_bfloat16* __restrict__ Bhi, const __nv_bfloat16* __restrict__ Blo,
    float* __restrict__ Y, float2* __restrict__ st) {
    extern __shared__ char smem[];
    unsigned sb = smem_u32(smem);
    const unsigned AH = 0, AL = 16384, BH = 32768, BL = 40960;
    const int O = 64, Kst = 64;
    int tid = threadIdx.x, wid = tid >> 5, lane = tid & 31;
    int wm = wid & 3, wn = wid >> 2;
    size_t mbase = (size_t)blockIdx.y * 128;
    int nbase = 0;

    float acc[2][4][4];
    #pragma unroll
    for (int i = 0; i < 2; i++)
        #pragma unroll
        for (int j = 0; j < 4; j++)
            #pragma unroll
            for (int r = 0; r < 4; r++) acc[i][j][r] = 0.f;

    // loads: A 128 rows x 2 chunks (k 0..15), B 64 rows x 2 chunks
    {
        int i = tid;            // 0..255 -> r = i>>1 (0..127), kc = i&1
        int r = i >> 1, kc = i & 1;
        unsigned sw = SW((unsigned)(r * 128 + kc * 16));
        const __nv_bfloat16* sa = Ahi + (mbase + r) * Kst + kc * 8;
        const __nv_bfloat16* sl = Alo + (mbase + r) * Kst + kc * 8;
        asm volatile("cp.async.ca.shared.global [%0], [%1], 16;" :: "r"(sb + AH + sw), "l"(sa));
        asm volatile("cp.async.ca.shared.global [%0], [%1], 16;" :: "r"(sb + AL + sw), "l"(sl));
        if (tid < 128) {
            int rb = tid >> 1, kb2 = tid & 1;
            unsigned swb = SW((unsigned)(rb * 128 + kb2 * 16));
            const __nv_bfloat16* ba = Bhi + (size_t)rb * Kst + kb2 * 8;
            const __nv_bfloat16* bb2 = Blo + (size_t)rb * Kst + kb2 * 8;
            asm volatile("cp.async.ca.shared.global [%0], [%1], 16;" :: "r"(sb + BH + swb), "l"(ba));
            asm volatile("cp.async.ca.shared.global [%0], [%1], 16;" :: "r"(sb + BL + swb), "l"(bb2));
        }
    }
    asm volatile("cp.async.commit_group;");
    asm volatile("cp.async.wait_group 0;");
    __syncthreads();

    // single k16 step (k0 = 0)
    {
        unsigned ah[2][4], al[2][4];
        {
            int arow = lane & 15, akk = (lane >> 4) << 3;
            #pragma unroll
            for (int mf = 0; mf < 2; mf++) {
                unsigned byte = (unsigned)((wm * 32 + mf * 16 + arow) * 128 + akk * 2);
                unsigned sw = SW(byte);
                ldsm4(ah[mf], sb + AH + sw);
                ldsm4(al[mf], sb + AL + sw);
            }
        }
        unsigned bh[4][2], bl[4][2];
        {
            int brow = ((lane >> 4) << 3) + (lane & 7);
            int bkk = ((lane >> 3) & 1) << 3;
            #pragma unroll
            for (int nf16 = 0; nf16 < 2; nf16++) {
                unsigned byte = (unsigned)((wn * 32 + nf16 * 16 + brow) * 128 + bkk * 2);
                unsigned sw = SW(byte);
                unsigned t[4];
                ldsm4(t, sb + BH + sw);
                bh[nf16 * 2][0] = t[0]; bh[nf16 * 2][1] = t[1];
                bh[nf16 * 2 + 1][0] = t[2]; bh[nf16 * 2 + 1][1] = t[3];
                ldsm4(t, sb + BL + sw);
                bl[nf16 * 2][0] = t[0]; bl[nf16 * 2][1] = t[1];
                bl[nf16 * 2 + 1][0] = t[2]; bl[nf16 * 2 + 1][1] = t[3];
            }
        }
        #pragma unroll
        for (int mf = 0; mf < 2; mf++)
            #pragma unroll
            for (int nf = 0; nf < 4; nf++) {
                mma_bf16(acc[mf][nf], ah[mf], bh[nf]);
                mma_bf16(acc[mf][nf], ah[mf], bl[nf]);
                mma_bf16(acc[mf][nf], al[mf], bh[nf]);
            }
    }

    // epilogue 1: point-major Y stores
    int g = lane >> 2, tg = lane & 3;
    #pragma unroll
    for (int mf = 0; mf < 2; mf++) {
        size_t row0 = mbase + wm * 32 + mf * 16;
        #pragma unroll
        for (int nf = 0; nf < 4; nf++) {
            int col = nbase + wn * 32 + nf * 8 + tg * 2;
            float2 v0 = {acc[mf][nf][0], acc[mf][nf][1]};
            float2 v1 = {acc[mf][nf][2], acc[mf][nf][3]};
            *(float2*)(Y + (row0 + g) * O + col) = v0;
            *(float2*)(Y + (row0 + 8 + g) * O + col) = v1;
        }
    }

    // epilogue 2: per-channel sum/sumsq
    float* red = (float*)(smem + 49152);
    __syncthreads();
    if (tid < 128) red[tid] = 0.f;
    __syncthreads();
    #pragma unroll
    for (int nf = 0; nf < 4; nf++) {
        #pragma unroll
        for (int c = 0; c < 2; c++) {
            float s = (acc[0][nf][c] + acc[0][nf][c + 2]) +
                      (acc[1][nf][c] + acc[1][nf][c + 2]);
            float q = (acc[0][nf][c] * acc[0][nf][c] + acc[0][nf][c + 2] * acc[0][nf][c + 2]) +
                      (acc[1][nf][c] * acc[1][nf][c] + acc[1][nf][c + 2] * acc[1][nf][c + 2]);
            #pragma unroll
            for (int off = 4; off < 32; off <<= 1) {
                s += __shfl_xor_sync(0xffffffffu, s, off);
                q += __shfl_xor_sync(0xffffffffu, q, off);
            }
            if (g == 0) {
                int lc = wn * 32 + nf * 8 + lane * 2 + c;
                atomicAdd(&red[2 * lc], s);
                atomicAdd(&red[2 * lc + 1], q);
            }
        }
    }
    __syncthreads();
    if (tid < 64) {
        atomicAdd(&st[nbase + tid].x, red[2 * tid]);
        atomicAdd(&st[nbase + tid].y, red[2 * tid + 1]);
    }
}

// ---------------- BN + lrelu + bf16 hi/lo split (a-layers) ----------------
__global__ void bn_split(const float* __restrict__ Y, const float2* __restrict__ st,
                         const float* __restrict__ gg, const float* __restrict__ bb,
                         int O, __nv_bfloat16* __restrict__ xh, __nv_bfloat16* __restrict__ xl) {
    size_t i4 = ((size_t)blockIdx.x * blockDim.x + threadIdx.x) * 4;
    int c0 = (int)(i4 & (size_t)(O - 1));
    float4 v = *(const float4*)(Y + i4);
    float o[4] = {v.x, v.y, v.z, v.w};
    __nv_bfloat16 h[4], l[4];
    #pragma unroll
    for (int j = 0; j < 4; j++) {
        int c = c0 + j;
        float2 s = st[c];
        float mu = s.x * (1.f / NN);
        float var = s.y * (1.f / NN) - mu * mu;
        float sc = rsqrtf(var + 1e-5f) * gg[c];
        float sh = bb[c] - mu * sc;
        float t = fmaf(o[j], sc, sh);
        t = t > 0.f ? t : NEG * t;
        split2(t, h[j], l[j]);
    }
    *(unsigned*)(xh + i4 + 0) = pack_bf2(h[0], h[1]);
    *(unsigned*)(xh + i4 + 2) = pack_bf2(h[2], h[3]);
    *(unsigned*)(xl + i4 + 0) = pack_bf2(l[0], l[1]);
    *(unsigned*)(xl + i4 + 2) = pack_bf2(l[2], l[3]);
}

// ---------------- BN + lrelu + gate + max over K (b-layers) ----------------
__global__ void bnmax_kernel(const float* __restrict__ Y, const float2* __restrict__ st,
                             const float* __restrict__ gg, const float* __restrict__ bb,
                             const float* __restrict__ gate, int M, int K, int O,
                             float* __restrict__ outf,
                             __nv_bfloat16* __restrict__ fh, __nv_bfloat16* __restrict__ fl) {
    int gw = (blockIdx.x * blockDim.x + threadIdx.x) >> 5;
    int lane = threadIdx.x & 31;
    if (gw >= B_ * M) return;
    int b = gw / M, m = gw - b * M;
    int base = gw * K;
    int J = O >> 5;
    float mx[8], sc[8], sh[8];
    for (int j = 0; j < J; j++) {
        int c = lane + 32 * j;
        float2 s = st[c];
        float mu = s.x * (1.f / NN);
        float var = s.y * (1.f / NN) - mu * mu;
        sc[j] = rsqrtf(var + 1e-5f) * gg[c];
        sh[j] = bb[c] - mu * sc[j];
        mx[j] = -3.4e38f;
    }
    for (int k = 0; k < K; k++) {
        float gt = gate[base + k];
        const float* row = Y + (size_t)(base + k) * O;
        for (int j = 0; j < J; j++) {
            float t = fmaf(row[lane + 32 * j], sc[j], sh[j]);
            t = t > 0.f ? t : NEG * t;
            mx[j] = fmaxf(mx[j], gt * t);
        }
    }
    if (fh) {
        size_t r = ((size_t)b * M + m) * O;
        for (int j = 0; j < J; j++) {
            __nv_bfloat16 h, l;
            split2(mx[j], h, l);
            fh[r + lane + 32 * j] = h;
            fl[r + lane + 32 * j] = l;
        }
    } else {
        for (int j = 0; j < J; j++)
            outf[((size_t)b * O + lane + 32 * j) * M + m] = mx[j];
    }
}

extern "C" void kernel_launch(void* const* d_in, const int* in_sizes, int n_in,
                              void* d_out, int out_size) {
    const float* xyz = (const float*)d_in[0];
    const float* w1a = (const float*)d_in[1];
    const float* g1a = (const float*)d_in[2];
    const float* b1a = (const float*)d_in[3];
    const float* w1b = (const float*)d_in[4];
    const float* g1b = (const float*)d_in[5];
    const float* b1b = (const float*)d_in[6];
    const float* w2a = (const float*)d_in[7];
    const float* g2a = (const float*)d_in[8];
    const float* b2a = (const float*)d_in[9];
    const float* w2b = (const float*)d_in[10];
    const float* g2b = (const float*)d_in[11];
    const float* b2b = (const float*)d_in[12];

    float *qs, *q1, *q2, *gate, *ya, *yb;
    __nv_bfloat16 *xh, *xl, *f1h, *f1l, *wh, *wl;
    float2* st;
    cudaGetSymbolAddress((void**)&qs, g_qs);
    cudaGetSymbolAddress((void**)&q1, g_q1);
    cudaGetSymbolAddress((void**)&q2, g_q2);
    cudaGetSymbolAddress((void**)&xh, g_xhi);
    cudaGetSymbolAddress((void**)&xl, g_xlo);
    cudaGetSymbolAddress((void**)&gate, g_gate);
    cudaGetSymbolAddress((void**)&ya, g_ya);
    cudaGetSymbolAddress((void**)&yb, g_yb);
    cudaGetSymbolAddress((void**)&f1h, g_f1h);
    cudaGetSymbolAddress((void**)&f1l, g_f1l);
    cudaGetSymbolAddress((void**)&wh, g_wh);
    cudaGetSymbolAddress((void**)&wl, g_wl);
    cudaGetSymbolAddress((void**)&st, g_stats4);
    float2 *st1a = st, *st1b = st + 256, *st2a = st + 512, *st2b = st + 768;

    const int HSM = 49152 + 512;
    cudaFuncSetAttribute(hgemm, cudaFuncAttributeMaxDynamicSharedMemorySize, HSM);
    cudaFuncSetAttribute(hgemm1a, cudaFuncAttributeMaxDynamicSharedMemorySize, HSM);

    const float r2a = (float)(0.15 * 0.15);
    const float r2b = (float)(0.3 * 0.3);

    cudaMemsetAsync(st, 0, 4 * 256 * sizeof(float2), 0);
    wsplit_kernel<<<4, 256>>>(w1a, w1b, w2a, w2b, wh, wl);

    // ---------- stage 1 ----------
    shift_kernel<<<(B_ * 512 + 255) / 256, 256>>>(xyz, qs, 512);
    fps_kernel<4><<<B_, 128>>>(qs, q1, 256);
    group_kernel<<<1024, 256>>>(q1, 256, xyz, 512, (const __nv_bfloat16*)0,
                                (const __nv_bfloat16*)0, r2a, 0.15f, 16, 64, xh, xl, gate);
    hgemm1a<<<dim3(1, NN / 128), 256, HSM>>>(xh, xl, wh, wl, ya, st1a);
    bn_split<<<(NN / 1024) * 64, 256>>>(ya, st1a, g1a, b1a, 64, xh, xl);
    hgemm<<<dim3(2, NN / 128), 256, HSM>>>(xh, xl, wh + 4096, wl + 4096, yb, 128, 64, st1b);
    bnmax_kernel<<<1024, 256>>>(yb, st1b, g1b, b1b, gate, 256, 16, 128,
                                (float*)0, f1h, f1l);

    // ---------- stage 2 ----------
    shift_kernel<<<(B_ * 256 + 255) / 256, 256>>>(q1, qs, 256);
    fps_kernel<2><<<B_, 128>>>(qs, q2, 128);
    group_kernel<<<512, 256>>>(q2, 128, q1, 256, f1h, f1l, r2b, 0.3f, 32, 192,
                               xh, xl, gate);
    hgemm<<<dim3(2, NN / 128), 256, HSM>>>(xh, xl, wh + 12288, wl + 12288, ya, 128, 192, st2a);
    bn_split<<<(NN / 1024) * 128, 256>>>(ya, st2a, g2a, b2a, 128, xh, xl);
    hgemm<<<dim3(4, NN / 128), 256, HSM>>>(xh, xl, wh + 36864, wl + 36864, yb, 256, 128, st2b);
    bnmax_kernel<<<512, 256>>>(yb, st2b, g2b, b2b, gate, 128, 32, 256,
                               (float*)d_out, (__nv_bfloat16*)0, (__nv_bfloat16*)0);
}